// round 10
// baseline (speedup 1.0000x reference)
#include <cuda_runtime.h>

// Problem constants (match reference)
#define K_VOX 12000
#define T_PTS 35
#define F_IN  7
#define D_DIM 10
#define H_DIM 400
#define W_DIM 352
#define C_OUT_DIM 128
#define EPSVAL 1e-3f

#define NCELLS (D_DIM * H_DIM * W_DIM)        // 1,408,000 cells (512B each)
#define NBMW   ((NCELLS + 31) / 32)           // 44,000 bitmap words

// Fused grid: period-8 interleave, 5 zero-role + 3 compute-role blocks.
#define NB_TOTAL 8000
#define ZERO_THREADS (5000 * 256)

// Prep kernel grid: 1500 dirty-cell blocks + 172 bitmap-clear blocks.
#define NPREP_VOX_BLK 1500
#define NPREP_BLK (NPREP_VOX_BLK + (NBMW + 255) / 256)

__device__ unsigned g_bitmap[NBMW];           // dirty-cell bitmap (176 KB)

// ---------------------------------------------------------------------------
// Kernel A: zero the 12000 dirty cells (6MB) and clear the bitmap.
// ---------------------------------------------------------------------------
__global__ __launch_bounds__(256) void prep_kernel(
    const int* __restrict__ coord, float* __restrict__ out)
{
    const int bid = blockIdx.x;
    const int tid = threadIdx.x;
    if (bid < NPREP_VOX_BLK) {
        // 8 voxels per block, 32 threads zero one 512B cell each
        const int k    = bid * 8 + (tid >> 5);
        const int lane = tid & 31;
        const int4 c = __ldg(&((const int4*)coord)[k]);
        const int base =
            (((c.x * D_DIM + c.y) * H_DIM + c.z) * W_DIM + c.w) * C_OUT_DIM;
        ((float4*)(out + base))[lane] = make_float4(0.f, 0.f, 0.f, 0.f);
    } else {
        const int w = (bid - NPREP_VOX_BLK) * 256 + tid;
        if (w < NBMW) g_bitmap[w] = 0u;
    }
}

// ---------------------------------------------------------------------------
// Kernel B: set dirty bits (after the clear completes).
// ---------------------------------------------------------------------------
__global__ __launch_bounds__(256) void bits_kernel(const int* __restrict__ coord)
{
    const int k = blockIdx.x * 256 + threadIdx.x;
    if (k >= K_VOX) return;
    const int4 c = __ldg(&((const int4*)coord)[k]);
    const int cell = ((c.x * D_DIM + c.y) * H_DIM + c.z) * W_DIM + c.w;
    atomicOr(&g_bitmap[cell >> 5], 1u << (cell & 31));
}

// ---------------------------------------------------------------------------
// Kernel C: fused — zero role streams zeros over all CLEAN cells (one uniform
// bitmap test per warp-iteration; each warp's 512B chunk is exactly one cell);
// compute role computes voxel features and atomicAdds directly into out
// (dirty cells pre-zeroed by Kernel A; zero role never touches them).
// ---------------------------------------------------------------------------
__global__ __launch_bounds__(256) void fused_kernel(
    const float* __restrict__ feat,     // [K, T, F]
    const float* __restrict__ w1,       // [F, 16]
    const float* __restrict__ b1,
    const float* __restrict__ gamma1, const float* __restrict__ beta1,
    const float* __restrict__ mean1,  const float* __restrict__ var1,
    const float* __restrict__ w2,       // [32, 64]
    const float* __restrict__ b2,
    const float* __restrict__ gamma2, const float* __restrict__ beta2,
    const float* __restrict__ mean2,  const float* __restrict__ var2,
    const int*   __restrict__ coord,    // [K, 4]
    float*       __restrict__ out,      // [1, D, H, W, 128]
    int n4)                             // out_size / 4 (float4 count)
{
    const int bid = blockIdx.x;
    const int tid = threadIdx.x;
    const int r = bid & 7;

    if (r < 5) {
        // ---------------- Zero role (skip dirty cells) ----------------
        const int zid = (bid >> 3) * 5 + r;
        float4* o4 = (float4*)out;
        const float4 z = make_float4(0.f, 0.f, 0.f, 0.f);
        for (int i = zid * 256 + tid; i < n4; i += ZERO_THREADS) {
            const int cell = i >> 5;            // uniform across the warp
            const unsigned w = __ldg(&g_bitmap[cell >> 5]);
            if (!((w >> (cell & 31)) & 1u)) o4[i] = z;
        }
        return;
    }

    // ---------------- Compute role ----------------
    const int cid = (bid >> 3) * 3 + (r - 5);   // 0..2999
    const int g   = tid >> 6;                   // group 0..3 (one voxel each)
    const int v   = tid & 63;                   // output channel within group
    const int k   = cid * 4 + g;                // voxel id

    __shared__ float sw1[F_IN * 16];
    __shared__ float sb1[16], ss1[16], so1[16], spw1b[16];
    __shared__ float sfeat[4][T_PTS * F_IN];
    __shared__ int   smask[4][T_PTS];
    __shared__ __align__(16) float pw1s[4][T_PTS * 16];
    __shared__ float sagg1[4][16];

    // Block-invariant stage-1 params
    if (tid < F_IN * 16) sw1[tid] = w1[tid];
    if (tid < 16) {
        float s = gamma1[tid] * rsqrtf(var1[tid] + EPSVAL);
        float o = beta1[tid] - mean1[tid] * s;
        float bb = b1[tid];
        ss1[tid] = s; so1[tid] = o; sb1[tid] = bb;
        spw1b[tid] = fmaxf(bb, 0.f) * s + o;    // pw1 of a fully-masked point
    }

    // Per-thread stage-2 params (thread owns channels v and 64+v)
    const float s2v = gamma2[v] * rsqrtf(var2[v] + EPSVAL);
    const float o2v = beta2[v] - mean2[v] * s2v;
    const float b2v = b2[v];
    const float pw2b = fmaxf(b2v, 0.f) * s2v + o2v;   // pw2 of a masked point

    float w2A[16], w2B[16];
#pragma unroll
    for (int j = 0; j < 16; j++) {
        w2A[j] = __ldg(&w2[j * 64 + v]);
        w2B[j] = __ldg(&w2[(16 + j) * 64 + v]);
    }

    // Load this group's point features
    for (int i = v; i < T_PTS * F_IN; i += 64)
        sfeat[g][i] = feat[k * (T_PTS * F_IN) + i];
    __syncthreads();

    // Mask: point valid iff max over its features != 0
    if (v < T_PTS) {
        float m = sfeat[g][v * F_IN];
#pragma unroll
        for (int f = 1; f < F_IN; f++) m = fmaxf(m, sfeat[g][v * F_IN + f]);
        smask[g][v] = (m != 0.f) ? 1 : 0;
    }
    __syncthreads();

    // Stage 1: pw1_eff[t][u] (masked rows take the constant pw1b[u])
    for (int e = v; e < T_PTS * 16; e += 64) {
        const int t = e >> 4, u = e & 15;
        float val;
        if (smask[g][t]) {
            float d = sb1[u];
#pragma unroll
            for (int f = 0; f < F_IN; f++)
                d = fmaf(sfeat[g][t * F_IN + f], sw1[f * 16 + u], d);
            val = fmaxf(d, 0.f) * ss1[u] + so1[u];
        } else {
            val = spw1b[u];
        }
        pw1s[g][e] = val;
    }
    __syncthreads();

    // agg1[u] = max over ALL t of pw1_eff (reference maxes pre-mask)
    if (v < 16) {
        float m = pw1s[g][v];
        for (int t = 1; t < T_PTS; t++) m = fmaxf(m, pw1s[g][t * 16 + v]);
        sagg1[g][v] = m;
    }
    __syncthreads();

    // Stage 2: per-channel dot over valid rows
    float aggdot = 0.f;
#pragma unroll
    for (int j = 0; j < 16; j++) aggdot = fmaf(sagg1[g][j], w2B[j], aggdot);
    const float base2 = b2v + aggdot;

    float vmax = -3.4e38f, amax = -3.4e38f;
    int anyInvalid = 0, anyValid = 0;
    for (int t = 0; t < T_PTS; t++) {
        if (smask[g][t]) {
            anyValid = 1;
            const float4* row = (const float4*)(pw1s[g] + t * 16);
            float4 r0 = row[0], r1 = row[1], r2 = row[2], r3 = row[3];
            float d0 = base2, d1 = 0.f;
            d0 = fmaf(r0.x, w2A[0], d0);  d1 = fmaf(r0.y, w2A[1], d1);
            d0 = fmaf(r0.z, w2A[2], d0);  d1 = fmaf(r0.w, w2A[3], d1);
            d0 = fmaf(r1.x, w2A[4], d0);  d1 = fmaf(r1.y, w2A[5], d1);
            d0 = fmaf(r1.z, w2A[6], d0);  d1 = fmaf(r1.w, w2A[7], d1);
            d0 = fmaf(r2.x, w2A[8], d0);  d1 = fmaf(r2.y, w2A[9], d1);
            d0 = fmaf(r2.z, w2A[10], d0); d1 = fmaf(r2.w, w2A[11], d1);
            d0 = fmaf(r3.x, w2A[12], d0); d1 = fmaf(r3.y, w2A[13], d1);
            d0 = fmaf(r3.z, w2A[14], d0); d1 = fmaf(r3.w, w2A[15], d1);
            float pw2 = fmaxf(d0 + d1, 0.f) * s2v + o2v;
            vmax = fmaxf(vmax, pw2);
            amax = fmaxf(amax, pw2);
        } else {
            anyInvalid = 1;
        }
    }

    float outA, outB;
    if (!anyValid) {
        outA = 0.f; outB = 0.f;
    } else if (anyInvalid) {
        amax = fmaxf(amax, pw2b);
        outA = fmaxf(vmax, 0.f);
        outB = fmaxf(amax, 0.f);
    } else {
        outA = vmax; outB = amax;
    }

    // Scatter-add directly (dirty cell pre-zeroed; duplicates accumulate)
    const int4 c = __ldg(&((const int4*)coord)[k]);
    const int base =
        (((c.x * D_DIM + c.y) * H_DIM + c.z) * W_DIM + c.w) * C_OUT_DIM;
    atomicAdd(out + base + v, outA);
    atomicAdd(out + base + 64 + v, outB);
}

// ---------------------------------------------------------------------------
extern "C" void kernel_launch(void* const* d_in, const int* in_sizes, int n_in,
                              void* d_out, int out_size) {
    const float* feat   = (const float*)d_in[0];
    const float* w1     = (const float*)d_in[1];
    const float* b1     = (const float*)d_in[2];
    const float* gamma1 = (const float*)d_in[3];
    const float* beta1  = (const float*)d_in[4];
    const float* mean1  = (const float*)d_in[5];
    const float* var1   = (const float*)d_in[6];
    const float* w2     = (const float*)d_in[7];
    const float* b2     = (const float*)d_in[8];
    const float* gamma2 = (const float*)d_in[9];
    const float* beta2  = (const float*)d_in[10];
    const float* mean2  = (const float*)d_in[11];
    const float* var2   = (const float*)d_in[12];
    const int*   coord  = (const int*)d_in[13];
    float* out = (float*)d_out;

    const int n4 = out_size / 4;
    prep_kernel<<<NPREP_BLK, 256>>>(coord, out);
    bits_kernel<<<(K_VOX + 255) / 256, 256>>>(coord);
    fused_kernel<<<NB_TOTAL, 256>>>(feat, w1, b1, gamma1, beta1, mean1, var1,
                                    w2, b2, gamma2, beta2, mean2, var2,
                                    coord, out, n4);
}